// round 1
// baseline (speedup 1.0000x reference)
#include <cuda_runtime.h>
#include <math.h>

#define HCH  512
#define NST  64
#define BS   8
#define LSEQ 2048
#define NFFT 4096

// module-static scratch (allowed; no runtime allocation)
__device__ float2 d_tw[NFFT / 2];                 // exp(-2*pi*i*j/4096)
__device__ float2 d_Kf[(size_t)HCH * NFFT];       // per-channel spectrum (bit-reversed order)

__device__ __forceinline__ float2 cmul(float2 a, float2 b) {
    return make_float2(fmaf(a.x, b.x, -a.y * b.y), fmaf(a.x, b.y, a.y * b.x));
}
__device__ __forceinline__ float2 cadd(float2 a, float2 b) { return make_float2(a.x + b.x, a.y + b.y); }
__device__ __forceinline__ float2 csub(float2 a, float2 b) { return make_float2(a.x - b.x, a.y - b.y); }

// ---------------------------------------------------------------------------
// Kernel A: twiddle table (double-precision accurate, stored fp32)
// ---------------------------------------------------------------------------
__global__ void tw_kernel() {
    int j = blockIdx.x * blockDim.x + threadIdx.x;
    if (j < NFFT / 2) {
        double a = -2.0 * 3.141592653589793238462643 * (double)j / (double)NFFT;
        d_tw[j] = make_float2((float)cos(a), (float)sin(a));
    }
}

// ---------------------------------------------------------------------------
// Kernel B: per-channel spectral kernel build.
// 1) Cauchy generating function at 2048 roots of unity
// 2) inverse FFT (2048) -> real K, zero-pad to 4096
// 3) forward FFT (4096) -> Kf (bit-reversed), stored to global
// ---------------------------------------------------------------------------
__global__ void kernel_spec(const float* __restrict__ Lr, const float* __restrict__ Li,
                            const float* __restrict__ Pr, const float* __restrict__ Pi,
                            const float* __restrict__ Br, const float* __restrict__ Bi,
                            const float* __restrict__ Cr, const float* __restrict__ Ci,
                            const float* __restrict__ logdt) {
    const int h   = blockIdx.x;
    const int tid = threadIdx.x;

    __shared__ float2 lam[NST], w00[NST], w01[NST], w10[NST];
    __shared__ float  w11[NST];
    extern __shared__ float2 x[];   // 4096 complex

    if (tid < NST) {
        int n = tid;
        lam[n] = make_float2(Lr[n], Li[n]);
        float2 P  = make_float2(Pr[n], Pi[n]);
        float2 Bv = make_float2(Br[n], Bi[n]);
        float2 Cc = make_float2(Cr[h * NST + n], -Ci[h * NST + n]);
        w00[n] = cmul(Cc, Bv);
        w01[n] = cmul(Cc, P);
        float2 Qc = make_float2(P.x, -P.y);
        w10[n] = cmul(Qc, Bv);
        w11[n] = P.x * P.x + P.y * P.y;     // conj(P)*P is real
    }
    __syncthreads();

    const float dt = expf(logdt[h]);
    const float g0 = 2.0f / dt;

    // ---- at_roots into x[0..2047] ----
    for (int l = tid; l < LSEQ; l += blockDim.x) {
        float2 at;
        if (l == LSEQ / 2) {
            // omega = -1 exactly in our table; take the analytic limit:
            // at -> dt * sum(conj(C)*B) / (1 - omega) = dt * sum(w00) / 2
            float2 s = make_float2(0.f, 0.f);
            for (int n = 0; n < NST; n++) s = cadd(s, w00[n]);
            at = make_float2(0.5f * dt * s.x, 0.5f * dt * s.y);
        } else {
            int j = 2 * l;   // omega = exp(-2*pi*i*l/2048) = tw4096[2l] (mod sign)
            float2 om = (j < NFFT / 2) ? d_tw[j]
                                       : make_float2(-d_tw[j - NFFT / 2].x, -d_tw[j - NFFT / 2].y);
            float2 den = make_float2(1.f + om.x, om.y);       // 1 + omega
            float2 num = make_float2(1.f - om.x, -om.y);      // 1 - omega
            float idl  = 1.f / (den.x * den.x + den.y * den.y);
            float2 c2  = make_float2(2.f * den.x * idl, -2.f * den.y * idl);  // 2/(1+omega)
            float2 gf  = cmul(num, make_float2(den.x, -den.y));               // (1-om)*conj(1+om)
            float2 g   = make_float2(g0 * gf.x * idl, g0 * gf.y * idl);       // (2/dt)(1-om)/(1+om)

            float2 k00 = {0.f, 0.f}, k01 = {0.f, 0.f}, k10 = {0.f, 0.f}, k11 = {0.f, 0.f};
#pragma unroll 8
            for (int n = 0; n < NST; n++) {
                float dx  = g.x - lam[n].x;
                float dy  = g.y - lam[n].y;
                float inv = 1.f / (dx * dx + dy * dy);
                float2 r  = make_float2(dx * inv, -dy * inv);   // 1/(g - Lambda_n)
                k00 = cadd(k00, cmul(w00[n], r));
                k01 = cadd(k01, cmul(w01[n], r));
                k10 = cadd(k10, cmul(w10[n], r));
                k11.x = fmaf(w11[n], r.x, k11.x);
                k11.y = fmaf(w11[n], r.y, k11.y);
            }
            float2 onep = make_float2(1.f + k11.x, k11.y);
            float  ip   = 1.f / (onep.x * onep.x + onep.y * onep.y);
            float2 invd = make_float2(onep.x * ip, -onep.y * ip);
            float2 t2   = cmul(cmul(k01, k10), invd);
            at = cmul(c2, csub(k00, t2));
        }
        x[l] = at;
    }
    __syncthreads();

    // ---- inverse FFT 2048 (DIF, conj twiddles): natural in -> bit-reversed out ----
    {
        int step = 2;                               // tw index stride = k * (4096/(2*mh))
        for (int mh = 1024; mh >= 1; mh >>= 1, step <<= 1) {
            for (int t = tid; t < 1024; t += blockDim.x) {
                int k  = t & (mh - 1);
                int i0 = 2 * t - k, i1 = i0 + mh;
                float2 a = x[i0], b = x[i1];
                x[i0] = cadd(a, b);
                float2 w = d_tw[k * step];
                w.y = -w.y;                          // inverse sign
                x[i1] = cmul(csub(a, b), w);
            }
            __syncthreads();
        }
    }
    // bit-reverse (11-bit) to natural order
    for (int i = tid; i < 2048; i += blockDim.x) {
        int r = __brev(i) >> 21;
        if (r > i) { float2 t = x[i]; x[i] = x[r]; x[r] = t; }
    }
    __syncthreads();
    // take real part, scale 1/2048, zero-pad upper half
    const float sc = 1.0f / 2048.0f;
    for (int i = tid; i < 2048; i += blockDim.x) x[i] = make_float2(x[i].x * sc, 0.f);
    for (int i = 2048 + tid; i < NFFT; i += blockDim.x) x[i] = make_float2(0.f, 0.f);
    __syncthreads();

    // ---- forward FFT 4096 (DIF): natural in -> bit-reversed out ----
    {
        int step = 1;
        for (int mh = 2048; mh >= 1; mh >>= 1, step <<= 1) {
            for (int t = tid; t < 2048; t += blockDim.x) {
                int k  = t & (mh - 1);
                int i0 = 2 * t - k, i1 = i0 + mh;
                float2 a = x[i0], b = x[i1];
                x[i0] = cadd(a, b);
                x[i1] = cmul(csub(a, b), d_tw[k * step]);
            }
            __syncthreads();
        }
    }
    float2* kf = d_Kf + (size_t)h * NFFT;
    for (int i = tid; i < NFFT; i += blockDim.x) kf[i] = x[i];
}

// ---------------------------------------------------------------------------
// Kernel C: per (b,h) causal FFT convolution + skip.
// forward DIF 4096 -> pointwise (bit-reversed, matched order) -> inverse DIT 4096
// ---------------------------------------------------------------------------
__global__ void kernel_conv(const float* __restrict__ u, const float* __restrict__ D,
                            float* __restrict__ y) {
    const int h   = blockIdx.x;
    const int b   = blockIdx.y;
    const int tid = threadIdx.x;
    extern __shared__ float2 x[];   // 4096 complex

    const float* ub = u + ((size_t)b * LSEQ) * HCH + h;
    for (int l = tid; l < LSEQ; l += blockDim.x)
        x[l] = make_float2(ub[(size_t)l * HCH], 0.f);
    for (int l = LSEQ + tid; l < NFFT; l += blockDim.x)
        x[l] = make_float2(0.f, 0.f);
    __syncthreads();

    // forward DIF 4096
    {
        int step = 1;
        for (int mh = 2048; mh >= 1; mh >>= 1, step <<= 1) {
            for (int t = tid; t < 2048; t += blockDim.x) {
                int k  = t & (mh - 1);
                int i0 = 2 * t - k, i1 = i0 + mh;
                float2 a = x[i0], bb = x[i1];
                x[i0] = cadd(a, bb);
                x[i1] = cmul(csub(a, bb), d_tw[k * step]);
            }
            __syncthreads();
        }
    }

    // pointwise multiply (both sides bit-reversed with identical permutation)
    const float2* kf = d_Kf + (size_t)h * NFFT;
    for (int i = tid; i < NFFT; i += blockDim.x) x[i] = cmul(x[i], kf[i]);
    __syncthreads();

    // inverse DIT 4096: bit-reversed in -> natural out, conj twiddles
    {
        int step = 2048;
        for (int mh = 1; mh <= 2048; mh <<= 1, step >>= 1) {
            for (int t = tid; t < 2048; t += blockDim.x) {
                int k  = t & (mh - 1);
                int i0 = 2 * t - k, i1 = i0 + mh;
                float2 a = x[i0];
                float2 w = d_tw[k * step];
                w.y = -w.y;
                float2 bb = cmul(x[i1], w);
                x[i0] = cadd(a, bb);
                x[i1] = csub(a, bb);
            }
            __syncthreads();
        }
    }

    const float Dh  = D[h];
    const float inv = 1.0f / (float)NFFT;
    float* yb = y + ((size_t)b * LSEQ) * HCH + h;
    for (int l = tid; l < LSEQ; l += blockDim.x) {
        float uu = ub[(size_t)l * HCH];
        yb[(size_t)l * HCH] = fmaf(x[l].x, inv, uu * Dh);
    }
}

// ---------------------------------------------------------------------------
extern "C" void kernel_launch(void* const* d_in, const int* in_sizes, int n_in,
                              void* d_out, int out_size) {
    const float* u   = (const float*)d_in[0];
    const float* Lr  = (const float*)d_in[1];
    const float* Li  = (const float*)d_in[2];
    const float* Pr  = (const float*)d_in[3];
    const float* Pi  = (const float*)d_in[4];
    const float* Br  = (const float*)d_in[5];
    const float* Bi  = (const float*)d_in[6];
    const float* Cr  = (const float*)d_in[7];
    const float* Ci  = (const float*)d_in[8];
    const float* ldt = (const float*)d_in[9];
    const float* D   = (const float*)d_in[10];
    float* y = (float*)d_out;

    const size_t smem = (size_t)NFFT * sizeof(float2);   // 32 KB

    tw_kernel<<<(NFFT / 2 + 255) / 256, 256>>>();
    kernel_spec<<<HCH, 256, smem>>>(Lr, Li, Pr, Pi, Br, Bi, Cr, Ci, ldt);
    kernel_conv<<<dim3(HCH, BS), 256, smem>>>(u, D, y);
}

// round 2
// speedup vs baseline: 3.4240x; 3.4240x over previous
#include <cuda_runtime.h>
#include <math.h>

#define HCH  512
#define NST  64
#define BS   8
#define LSEQ 2048
#define NFFT 4096
#define SIDX(i) ((i) + ((i) >> 4))
#define SPAD (NFFT + (NFFT >> 4))   // 4352 float2 = 34816 B

// module-static scratch (no runtime allocation)
__device__ float2 d_tw[NFFT / 2];                 // W4096^j = exp(-2*pi*i*j/4096)
__device__ float2 d_Kf[(size_t)HCH * NFFT];       // [h][j*256 + t] holding bit-rev position p=16t+j

// W16^m = exp(-2*pi*i*m/16), m=0..7
__constant__ float2 C16[8] = {
    { 1.0f,           0.0f},
    { 0.92387953251f, -0.38268343236f},
    { 0.70710678119f, -0.70710678119f},
    { 0.38268343236f, -0.92387953251f},
    { 0.0f,          -1.0f},
    {-0.38268343236f, -0.92387953251f},
    {-0.70710678119f, -0.70710678119f},
    {-0.92387953251f, -0.38268343236f},
};

__device__ __forceinline__ float2 cmul(float2 a, float2 b) {
    return make_float2(fmaf(a.x, b.x, -a.y * b.y), fmaf(a.x, b.y, a.y * b.x));
}
__device__ __forceinline__ float2 cmulj(float2 a, float2 b) {   // a * conj(b)
    return make_float2(fmaf(a.x, b.x, a.y * b.y), fmaf(a.y, b.x, -a.x * b.y));
}
__device__ __forceinline__ float2 cadd(float2 a, float2 b) { return make_float2(a.x + b.x, a.y + b.y); }
__device__ __forceinline__ float2 csub(float2 a, float2 b) { return make_float2(a.x - b.x, a.y - b.y); }

// ---------------------------------------------------------------------------
// 16-point register FFT blocks. Data layout: thread owns positions
// p = base-pattern indexed by j; twiddle exponent = 2^{q-1}*e + 256*2^{q-1}*(j mod 2^{4-q}),
// passed in as w1 = W4096^e.
// ---------------------------------------------------------------------------
__device__ __forceinline__ void fwd16(float2* v, float2 w1) {
    float2 w2 = cmul(w1, w1), w4 = cmul(w2, w2), w8 = cmul(w4, w4);
#pragma unroll
    for (int j = 0; j < 8; j++) {                  // mh ~ stride 8 in j
        float2 tw = cmul(w1, C16[j]);
        float2 a = v[j], bb = v[j + 8];
        v[j] = cadd(a, bb);
        v[j + 8] = cmul(csub(a, bb), tw);
    }
#pragma unroll
    for (int g = 0; g < 16; g += 8)
#pragma unroll
        for (int j = 0; j < 4; j++) {
            float2 tw = cmul(w2, C16[2 * j]);
            float2 a = v[g + j], bb = v[g + j + 4];
            v[g + j] = cadd(a, bb);
            v[g + j + 4] = cmul(csub(a, bb), tw);
        }
#pragma unroll
    for (int g = 0; g < 16; g += 4)
#pragma unroll
        for (int j = 0; j < 2; j++) {
            float2 tw = cmul(w4, C16[4 * j]);
            float2 a = v[g + j], bb = v[g + j + 2];
            v[g + j] = cadd(a, bb);
            v[g + j + 2] = cmul(csub(a, bb), tw);
        }
#pragma unroll
    for (int g = 0; g < 16; g += 2) {
        float2 a = v[g], bb = v[g + 1];
        v[g] = cadd(a, bb);
        v[g + 1] = cmul(csub(a, bb), w8);
    }
}

__device__ __forceinline__ void inv16(float2* v, float2 w1) {
    float2 c1 = make_float2(w1.x, -w1.y);
    float2 c2 = cmul(c1, c1), c4 = cmul(c2, c2), c8 = cmul(c4, c4);
#pragma unroll
    for (int g = 0; g < 16; g += 2) {              // mh=1 analog, tw = conj(w8)
        float2 tb = cmul(v[g + 1], c8);
        float2 a = v[g];
        v[g] = cadd(a, tb);
        v[g + 1] = csub(a, tb);
    }
#pragma unroll
    for (int g = 0; g < 16; g += 4)
#pragma unroll
        for (int j = 0; j < 2; j++) {
            float2 tw = cmulj(c4, C16[4 * j]);
            float2 tb = cmul(v[g + j + 2], tw);
            float2 a = v[g + j];
            v[g + j] = cadd(a, tb);
            v[g + j + 2] = csub(a, tb);
        }
#pragma unroll
    for (int g = 0; g < 16; g += 8)
#pragma unroll
        for (int j = 0; j < 4; j++) {
            float2 tw = cmulj(c2, C16[2 * j]);
            float2 tb = cmul(v[g + j + 4], tw);
            float2 a = v[g + j];
            v[g + j] = cadd(a, tb);
            v[g + j + 4] = csub(a, tb);
        }
#pragma unroll
    for (int j = 0; j < 8; j++) {
        float2 tw = cmulj(c1, C16[j]);
        float2 tb = cmul(v[j + 8], tw);
        float2 a = v[j];
        v[j] = cadd(a, tb);
        v[j + 8] = csub(a, tb);
    }
}

// ---------------------------------------------------------------------------
// Kernel A: twiddle table
// ---------------------------------------------------------------------------
__global__ void tw_kernel() {
    int j = blockIdx.x * blockDim.x + threadIdx.x;
    if (j < NFFT / 2) {
        double a = -2.0 * 3.141592653589793238462643 * (double)j / (double)NFFT;
        d_tw[j] = make_float2((float)cos(a), (float)sin(a));
    }
}

// ---------------------------------------------------------------------------
// Kernel B: per-channel spectral kernel build.
// ---------------------------------------------------------------------------
__global__ void __launch_bounds__(256) kernel_spec(
        const float* __restrict__ Lr, const float* __restrict__ Li,
        const float* __restrict__ Pr, const float* __restrict__ Pi,
        const float* __restrict__ Br, const float* __restrict__ Bi,
        const float* __restrict__ Cr, const float* __restrict__ Ci,
        const float* __restrict__ logdt) {
    const int h   = blockIdx.x;
    const int tid = threadIdx.x;

    __shared__ float2 lam[NST], w00[NST], w01[NST], w10[NST];
    __shared__ float  w11[NST];
    extern __shared__ float2 x[];   // SPAD float2

    if (tid < NST) {
        int n = tid;
        lam[n] = make_float2(Lr[n], Li[n]);
        float2 P  = make_float2(Pr[n], Pi[n]);
        float2 Bv = make_float2(Br[n], Bi[n]);
        float2 Cc = make_float2(Cr[h * NST + n], -Ci[h * NST + n]);
        w00[n] = cmul(Cc, Bv);
        w01[n] = cmul(Cc, P);
        float2 Qc = make_float2(P.x, -P.y);
        w10[n] = cmul(Qc, Bv);
        w11[n] = P.x * P.x + P.y * P.y;
    }
    __syncthreads();

    const float dt = expf(logdt[h]);
    const float g0 = 2.0f / dt;

    // ---- at_roots into x[0..2047] (natural order) ----
    for (int l = tid; l < LSEQ; l += blockDim.x) {
        float2 at;
        if (l == LSEQ / 2) {
            float2 s = make_float2(0.f, 0.f);
            for (int n = 0; n < NST; n++) s = cadd(s, w00[n]);
            at = make_float2(0.5f * dt * s.x, 0.5f * dt * s.y);
        } else {
            int j = 2 * l;
            float2 om = (j < NFFT / 2) ? d_tw[j]
                                       : make_float2(-d_tw[j - NFFT / 2].x, -d_tw[j - NFFT / 2].y);
            float2 den = make_float2(1.f + om.x, om.y);
            float2 num = make_float2(1.f - om.x, -om.y);
            float idl  = __fdividef(1.f, den.x * den.x + den.y * den.y);
            float2 c2  = make_float2(2.f * den.x * idl, -2.f * den.y * idl);
            float2 gf  = cmul(num, make_float2(den.x, -den.y));
            float2 g   = make_float2(g0 * gf.x * idl, g0 * gf.y * idl);

            float2 k00 = {0.f, 0.f}, k01 = {0.f, 0.f}, k10 = {0.f, 0.f}, k11 = {0.f, 0.f};
#pragma unroll 8
            for (int n = 0; n < NST; n++) {
                float dx  = g.x - lam[n].x;
                float dy  = g.y - lam[n].y;
                float inv = __fdividef(1.f, dx * dx + dy * dy);
                float2 r  = make_float2(dx * inv, -dy * inv);
                k00 = cadd(k00, cmul(w00[n], r));
                k01 = cadd(k01, cmul(w01[n], r));
                k10 = cadd(k10, cmul(w10[n], r));
                k11.x = fmaf(w11[n], r.x, k11.x);
                k11.y = fmaf(w11[n], r.y, k11.y);
            }
            float2 onep = make_float2(1.f + k11.x, k11.y);
            float  ip   = __fdividef(1.f, onep.x * onep.x + onep.y * onep.y);
            float2 invd = make_float2(onep.x * ip, -onep.y * ip);
            float2 t2   = cmul(cmul(k01, k10), invd);
            at = cmul(c2, csub(k00, t2));
        }
        x[SIDX(l)] = at;
    }
    __syncthreads();

    // ---- inverse FFT 2048 (radix-2 DIF, conj tw): natural -> bit-reversed ----
    {
        int step = 2;
        for (int mh = 1024; mh >= 1; mh >>= 1, step <<= 1) {
            for (int t = tid; t < 1024; t += blockDim.x) {
                int k  = t & (mh - 1);
                int i0 = 2 * t - k, i1 = i0 + mh;
                float2 a = x[SIDX(i0)], b = x[SIDX(i1)];
                x[SIDX(i0)] = cadd(a, b);
                float2 w = d_tw[k * step];
                w.y = -w.y;
                x[SIDX(i1)] = cmul(csub(a, b), w);
            }
            __syncthreads();
        }
    }
    // bit-reverse (11-bit) to natural order
    for (int i = tid; i < 2048; i += blockDim.x) {
        int r = __brev(i) >> 21;
        if (r > i) { float2 t = x[SIDX(i)]; x[SIDX(i)] = x[SIDX(r)]; x[SIDX(r)] = t; }
    }
    __syncthreads();
    const float sc = 1.0f / 2048.0f;
    for (int i = tid; i < 2048; i += blockDim.x) {
        float2 t = x[SIDX(i)];
        x[SIDX(i)] = make_float2(t.x * sc, 0.f);
    }
    for (int i = 2048 + tid; i < NFFT; i += blockDim.x) x[SIDX(i)] = make_float2(0.f, 0.f);
    __syncthreads();

    // ---- forward FFT 4096: 3 register-radix-16 passes ----
    float2 v[16];
#pragma unroll
    for (int j = 0; j < 16; j++) v[j] = x[SIDX(tid + 256 * j)];
    fwd16(v, d_tw[tid]);
#pragma unroll
    for (int j = 0; j < 16; j++) x[SIDX(tid + 256 * j)] = v[j];
    __syncthreads();

    const int base2 = ((tid >> 4) << 8) + (tid & 15);
#pragma unroll
    for (int j = 0; j < 16; j++) v[j] = x[SIDX(base2 + 16 * j)];
    fwd16(v, d_tw[(tid & 15) << 4]);
#pragma unroll
    for (int j = 0; j < 16; j++) x[SIDX(base2 + 16 * j)] = v[j];
    __syncthreads();

#pragma unroll
    for (int j = 0; j < 16; j++) v[j] = x[SIDX(16 * tid + j)];
    fwd16(v, make_float2(1.f, 0.f));

    // store in conv-friendly layout: d_Kf[h][j*256 + tid] (coalesced)
    float2* kf = d_Kf + (size_t)h * NFFT;
#pragma unroll
    for (int j = 0; j < 16; j++) kf[j * 256 + tid] = v[j];
}

// ---------------------------------------------------------------------------
// Kernel C: per (b,h) FFT convolution + skip.  256 thr, 16 cplx/thread.
// ---------------------------------------------------------------------------
__global__ void __launch_bounds__(256) kernel_conv(
        const float* __restrict__ u, const float* __restrict__ D,
        float* __restrict__ y) {
    const int h = blockIdx.x;
    const int b = blockIdx.y;
    const int t = threadIdx.x;
    extern __shared__ float2 x[];   // SPAD float2

    const float* ub = u + ((size_t)b * LSEQ) * HCH + h;
    float2 v[16];
    float  us[8];
#pragma unroll
    for (int j = 0; j < 8; j++) {
        us[j] = ub[(size_t)(t + 256 * j) * HCH];
        v[j] = make_float2(us[j], 0.f);
    }
#pragma unroll
    for (int j = 8; j < 16; j++) v[j] = make_float2(0.f, 0.f);

    // forward 4096
    const float2 w1 = d_tw[t];
    fwd16(v, w1);
#pragma unroll
    for (int j = 0; j < 16; j++) x[SIDX(t + 256 * j)] = v[j];
    __syncthreads();

    const int base2 = ((t >> 4) << 8) + (t & 15);
    const float2 wp2 = d_tw[(t & 15) << 4];
#pragma unroll
    for (int j = 0; j < 16; j++) v[j] = x[SIDX(base2 + 16 * j)];
    fwd16(v, wp2);
#pragma unroll
    for (int j = 0; j < 16; j++) x[SIDX(base2 + 16 * j)] = v[j];
    __syncthreads();

#pragma unroll
    for (int j = 0; j < 16; j++) v[j] = x[SIDX(16 * t + j)];
    fwd16(v, make_float2(1.f, 0.f));

    // pointwise multiply in registers (both sides in identical bit-rev order)
    const float2* kf = d_Kf + (size_t)h * NFFT;
#pragma unroll
    for (int j = 0; j < 16; j++) v[j] = cmul(v[j], kf[j * 256 + t]);

    // inverse 4096
    inv16(v, make_float2(1.f, 0.f));
#pragma unroll
    for (int j = 0; j < 16; j++) x[SIDX(16 * t + j)] = v[j];
    __syncthreads();

#pragma unroll
    for (int j = 0; j < 16; j++) v[j] = x[SIDX(base2 + 16 * j)];
    inv16(v, wp2);
#pragma unroll
    for (int j = 0; j < 16; j++) x[SIDX(base2 + 16 * j)] = v[j];
    __syncthreads();

#pragma unroll
    for (int j = 0; j < 16; j++) v[j] = x[SIDX(t + 256 * j)];
    inv16(v, w1);

    const float Dh  = D[h];
    const float inv = 1.0f / (float)NFFT;
    float* yb = y + ((size_t)b * LSEQ) * HCH + h;
#pragma unroll
    for (int j = 0; j < 8; j++)
        yb[(size_t)(t + 256 * j) * HCH] = fmaf(v[j].x, inv, us[j] * Dh);
}

// ---------------------------------------------------------------------------
extern "C" void kernel_launch(void* const* d_in, const int* in_sizes, int n_in,
                              void* d_out, int out_size) {
    const float* u   = (const float*)d_in[0];
    const float* Lr  = (const float*)d_in[1];
    const float* Li  = (const float*)d_in[2];
    const float* Pr  = (const float*)d_in[3];
    const float* Pi  = (const float*)d_in[4];
    const float* Br  = (const float*)d_in[5];
    const float* Bi  = (const float*)d_in[6];
    const float* Cr  = (const float*)d_in[7];
    const float* Ci  = (const float*)d_in[8];
    const float* ldt = (const float*)d_in[9];
    const float* D   = (const float*)d_in[10];
    float* y = (float*)d_out;

    const size_t smem = (size_t)SPAD * sizeof(float2);   // 34816 B

    tw_kernel<<<(NFFT / 2 + 255) / 256, 256>>>();
    kernel_spec<<<HCH, 256, smem>>>(Lr, Li, Pr, Pi, Br, Bi, Cr, Ci, ldt);
    kernel_conv<<<dim3(HCH, BS), 256, smem>>>(u, D, y);
}

// round 4
// speedup vs baseline: 3.9793x; 1.1622x over previous
#include <cuda_runtime.h>
#include <math.h>

#define HCH  512
#define NST  64
#define BS   8
#define LSEQ 2048
#define NFFT 4096
#define SIDX(i) ((i) + ((i) >> 4))
#define SPAD (NFFT + (NFFT >> 4))   // 4352 float2 = 34816 B

// per-channel spectrum, layout [h][j*256 + t] holding bit-rev position p=16t+j
__device__ float2 d_Kf[(size_t)HCH * NFFT];

// W16^m = exp(-2*pi*i*m/16), m=0..7
__constant__ float2 C16[8] = {
    { 1.0f,           0.0f},
    { 0.92387953251f, -0.38268343236f},
    { 0.70710678119f, -0.70710678119f},
    { 0.38268343236f, -0.92387953251f},
    { 0.0f,          -1.0f},
    {-0.38268343236f, -0.92387953251f},
    {-0.70710678119f, -0.70710678119f},
    {-0.92387953251f, -0.38268343236f},
};

// brev4 lookup (compile-time foldable in unrolled loops)
__constant__ int BR4[16] = {0, 8, 4, 12, 2, 10, 6, 14, 1, 9, 5, 13, 3, 11, 7, 15};

__device__ __forceinline__ float2 cmul(float2 a, float2 b) {
    return make_float2(fmaf(a.x, b.x, -a.y * b.y), fmaf(a.x, b.y, a.y * b.x));
}
__device__ __forceinline__ float2 cmulj(float2 a, float2 b) {   // a * conj(b)
    return make_float2(fmaf(a.x, b.x, a.y * b.y), fmaf(a.y, b.x, -a.x * b.y));
}
__device__ __forceinline__ float2 cadd(float2 a, float2 b) { return make_float2(a.x + b.x, a.y + b.y); }
__device__ __forceinline__ float2 csub(float2 a, float2 b) { return make_float2(a.x - b.x, a.y - b.y); }

// W4096^j = exp(-2*pi*i*j/4096), exact-argument via sincospif
__device__ __forceinline__ float2 tw4096(int j) {
    float s, c;
    sincospif((float)j * (1.0f / 2048.0f), &s, &c);
    return make_float2(c, -s);
}
// conj(W4096^j)
__device__ __forceinline__ float2 tw4096c(int j) {
    float s, c;
    sincospif((float)j * (1.0f / 2048.0f), &s, &c);
    return make_float2(c, s);
}

// ---------------------------------------------------------------------------
// 16-point register FFT blocks (layout: 3 passes = full radix-2 DIF,
// position p ends holding frequency brev12(p)).
// ---------------------------------------------------------------------------
__device__ __forceinline__ void fwd16(float2* v, float2 w1) {
    float2 w2 = cmul(w1, w1), w4 = cmul(w2, w2), w8 = cmul(w4, w4);
#pragma unroll
    for (int j = 0; j < 8; j++) {
        float2 tw = cmul(w1, C16[j]);
        float2 a = v[j], bb = v[j + 8];
        v[j] = cadd(a, bb);
        v[j + 8] = cmul(csub(a, bb), tw);
    }
#pragma unroll
    for (int g = 0; g < 16; g += 8)
#pragma unroll
        for (int j = 0; j < 4; j++) {
            float2 tw = cmul(w2, C16[2 * j]);
            float2 a = v[g + j], bb = v[g + j + 4];
            v[g + j] = cadd(a, bb);
            v[g + j + 4] = cmul(csub(a, bb), tw);
        }
#pragma unroll
    for (int g = 0; g < 16; g += 4)
#pragma unroll
        for (int j = 0; j < 2; j++) {
            float2 tw = cmul(w4, C16[4 * j]);
            float2 a = v[g + j], bb = v[g + j + 2];
            v[g + j] = cadd(a, bb);
            v[g + j + 2] = cmul(csub(a, bb), tw);
        }
#pragma unroll
    for (int g = 0; g < 16; g += 2) {
        float2 a = v[g], bb = v[g + 1];
        v[g] = cadd(a, bb);
        v[g + 1] = cmul(csub(a, bb), w8);
    }
}

__device__ __forceinline__ void inv16(float2* v, float2 w1) {
    float2 c1 = make_float2(w1.x, -w1.y);
    float2 c2 = cmul(c1, c1), c4 = cmul(c2, c2), c8 = cmul(c4, c4);
#pragma unroll
    for (int g = 0; g < 16; g += 2) {
        float2 tb = cmul(v[g + 1], c8);
        float2 a = v[g];
        v[g] = cadd(a, tb);
        v[g + 1] = csub(a, tb);
    }
#pragma unroll
    for (int g = 0; g < 16; g += 4)
#pragma unroll
        for (int j = 0; j < 2; j++) {
            float2 tw = cmulj(c4, C16[4 * j]);
            float2 tb = cmul(v[g + j + 2], tw);
            float2 a = v[g + j];
            v[g + j] = cadd(a, tb);
            v[g + j + 2] = csub(a, tb);
        }
#pragma unroll
    for (int g = 0; g < 16; g += 8)
#pragma unroll
        for (int j = 0; j < 4; j++) {
            float2 tw = cmulj(c2, C16[2 * j]);
            float2 tb = cmul(v[g + j + 4], tw);
            float2 a = v[g + j];
            v[g + j] = cadd(a, tb);
            v[g + j + 4] = csub(a, tb);
        }
#pragma unroll
    for (int j = 0; j < 8; j++) {
        float2 tw = cmulj(c1, C16[j]);
        float2 tb = cmul(v[j + 8], tw);
        float2 a = v[j];
        v[j] = cadd(a, tb);
        v[j + 8] = csub(a, tb);
    }
}

// ---------------------------------------------------------------------------
// Kernel B: per-channel spectral kernel build.
// ---------------------------------------------------------------------------
__global__ void __launch_bounds__(256) kernel_spec(
        const float* __restrict__ Lr, const float* __restrict__ Li,
        const float* __restrict__ Pr, const float* __restrict__ Pi,
        const float* __restrict__ Br, const float* __restrict__ Bi,
        const float* __restrict__ Cr, const float* __restrict__ Ci,
        const float* __restrict__ logdt) {
    const int h   = blockIdx.x;
    const int tid = threadIdx.x;

    __shared__ float2 lam[NST], w00[NST], w01[NST], w10[NST];
    __shared__ float  w11[NST];
    extern __shared__ float2 x[];   // SPAD float2

    if (tid < NST) {
        int n = tid;
        lam[n] = make_float2(Lr[n], Li[n]);
        float2 P  = make_float2(Pr[n], Pi[n]);
        float2 Bv = make_float2(Br[n], Bi[n]);
        float2 Cc = make_float2(Cr[h * NST + n], -Ci[h * NST + n]);
        w00[n] = cmul(Cc, Bv);
        w01[n] = cmul(Cc, P);
        float2 Qc = make_float2(P.x, -P.y);
        w10[n] = cmul(Qc, Bv);
        w11[n] = P.x * P.x + P.y * P.y;
    }
    __syncthreads();

    const float dt = expf(logdt[h]);
    const float g0 = 2.0f / dt;

    // ---- at_roots into x[0..2047] (natural order) ----
    for (int l = tid; l < LSEQ; l += blockDim.x) {
        float2 at;
        if (l == LSEQ / 2) {
            float2 s = make_float2(0.f, 0.f);
            for (int n = 0; n < NST; n++) s = cadd(s, w00[n]);
            at = make_float2(0.5f * dt * s.x, 0.5f * dt * s.y);
        } else {
            // omega = exp(-2*pi*i*l/2048)
            float ss, cc;
            sincospif((float)l * (1.0f / 1024.0f), &ss, &cc);
            float2 om = make_float2(cc, -ss);
            float2 den = make_float2(1.f + om.x, om.y);
            float2 num = make_float2(1.f - om.x, -om.y);
            float idl  = __fdividef(1.f, den.x * den.x + den.y * den.y);
            float2 c2  = make_float2(2.f * den.x * idl, -2.f * den.y * idl);
            float2 gf  = cmul(num, make_float2(den.x, -den.y));
            float2 g   = make_float2(g0 * gf.x * idl, g0 * gf.y * idl);

            float2 k00 = {0.f, 0.f}, k01 = {0.f, 0.f}, k10 = {0.f, 0.f}, k11 = {0.f, 0.f};
#pragma unroll 8
            for (int n = 0; n < NST; n++) {
                float dx  = g.x - lam[n].x;
                float dy  = g.y - lam[n].y;
                float inv = __fdividef(1.f, dx * dx + dy * dy);
                float2 r  = make_float2(dx * inv, -dy * inv);
                k00 = cadd(k00, cmul(w00[n], r));
                k01 = cadd(k01, cmul(w01[n], r));
                k10 = cadd(k10, cmul(w10[n], r));
                k11.x = fmaf(w11[n], r.x, k11.x);
                k11.y = fmaf(w11[n], r.y, k11.y);
            }
            float2 onep = make_float2(1.f + k11.x, k11.y);
            float  ip   = __fdividef(1.f, onep.x * onep.x + onep.y * onep.y);
            float2 invd = make_float2(onep.x * ip, -onep.y * ip);
            float2 t2   = cmul(cmul(k01, k10), invd);
            at = cmul(c2, csub(k00, t2));
        }
        x[SIDX(l)] = at;
    }
    __syncthreads();

    // ---- inverse FFT 2048 (radix-2 DIF, conj tw): natural -> bit-reversed ----
    {
        int step = 2;
        for (int mh = 1024; mh >= 1; mh >>= 1, step <<= 1) {
            for (int t = tid; t < 1024; t += blockDim.x) {
                int k  = t & (mh - 1);
                int i0 = 2 * t - k, i1 = i0 + mh;
                float2 a = x[SIDX(i0)], b = x[SIDX(i1)];
                x[SIDX(i0)] = cadd(a, b);
                x[SIDX(i1)] = cmul(csub(a, b), tw4096c(k * step));
            }
            __syncthreads();
        }
    }
    // bit-reverse (11-bit) to natural order
    for (int i = tid; i < 2048; i += blockDim.x) {
        int r = __brev(i) >> 21;
        if (r > i) { float2 t = x[SIDX(i)]; x[SIDX(i)] = x[SIDX(r)]; x[SIDX(r)] = t; }
    }
    __syncthreads();
    const float sc = 1.0f / 2048.0f;
    for (int i = tid; i < 2048; i += blockDim.x) {
        float2 t = x[SIDX(i)];
        x[SIDX(i)] = make_float2(t.x * sc, 0.f);
    }
    for (int i = 2048 + tid; i < NFFT; i += blockDim.x) x[SIDX(i)] = make_float2(0.f, 0.f);
    __syncthreads();

    // ---- forward FFT 4096: 3 register-radix-16 passes ----
    float2 v[16];
#pragma unroll
    for (int j = 0; j < 16; j++) v[j] = x[SIDX(tid + 256 * j)];
    fwd16(v, tw4096(tid));
#pragma unroll
    for (int j = 0; j < 16; j++) x[SIDX(tid + 256 * j)] = v[j];
    __syncthreads();

    const int base2 = ((tid >> 4) << 8) + (tid & 15);
#pragma unroll
    for (int j = 0; j < 16; j++) v[j] = x[SIDX(base2 + 16 * j)];
    fwd16(v, tw4096((tid & 15) << 4));
#pragma unroll
    for (int j = 0; j < 16; j++) x[SIDX(base2 + 16 * j)] = v[j];
    __syncthreads();

#pragma unroll
    for (int j = 0; j < 16; j++) v[j] = x[SIDX(16 * tid + j)];
    fwd16(v, make_float2(1.f, 0.f));

    float2* kf = d_Kf + (size_t)h * NFFT;
#pragma unroll
    for (int j = 0; j < 16; j++) kf[j * 256 + tid] = v[j];
}

// ---------------------------------------------------------------------------
// Kernel C: packed two-channel FFT convolution + skip.
// CTA = (h-pair, b). z = u[2h] + i*u[2h+1]; one fwd + one inv FFT per pair.
// S(k) = Z(k)*(Ka+Kb)/2 + conj(Z(N-k))*(Ka-Kb)/2
// ---------------------------------------------------------------------------
__global__ void __launch_bounds__(256) kernel_conv(
        const float* __restrict__ u, const float* __restrict__ D,
        float* __restrict__ y) {
    const int hp = blockIdx.x;                 // channel pair: (2hp, 2hp+1)
    const int b  = blockIdx.y;
    const int t  = threadIdx.x;
    extern __shared__ float2 x[];   // SPAD float2

    // u[b][l][2hp..2hp+1] is a contiguous, 8B-aligned float2
    const float2* uf2 = (const float2*)(u + (size_t)b * LSEQ * HCH) + hp;
    float2 v[16];
    float2 us[8];
#pragma unroll
    for (int j = 0; j < 8; j++) {
        us[j] = uf2[(size_t)(t + 256 * j) * (HCH / 2)];
        v[j] = us[j];
    }
#pragma unroll
    for (int j = 8; j < 16; j++) v[j] = make_float2(0.f, 0.f);

    // ---- forward 4096 ----
    const float2 w1 = tw4096(t);
    fwd16(v, w1);
#pragma unroll
    for (int j = 0; j < 16; j++) x[SIDX(t + 256 * j)] = v[j];
    __syncthreads();

    const int base2 = ((t >> 4) << 8) + (t & 15);
    const float2 wp2 = tw4096((t & 15) << 4);
#pragma unroll
    for (int j = 0; j < 16; j++) v[j] = x[SIDX(base2 + 16 * j)];
    fwd16(v, wp2);
#pragma unroll
    for (int j = 0; j < 16; j++) x[SIDX(base2 + 16 * j)] = v[j];
    __syncthreads();

#pragma unroll
    for (int j = 0; j < 16; j++) v[j] = x[SIDX(16 * t + j)];
    fwd16(v, make_float2(1.f, 0.f));
    // v[j] = Z at position p=16t+j, i.e. frequency k = brev12(p)

    // ---- natural-frequency exchange for Hermitian split ----
    const int rb_t = __brev(t) >> 24;          // brev8(t)
    __syncthreads();                            // others may still be reading pass-3 inputs
#pragma unroll
    for (int j = 0; j < 16; j++)
        x[SIDX((BR4[j] << 8) | rb_t)] = v[j];
    __syncthreads();

    const float2* kfa = d_Kf + (size_t)(2 * hp) * NFFT;
    const float2* kfb = d_Kf + (size_t)(2 * hp + 1) * NFFT;
#pragma unroll
    for (int j = 0; j < 16; j++) {
        int k  = (BR4[j] << 8) | rb_t;
        int km = (NFFT - k) & (NFFT - 1);
        float2 Zm = x[SIDX(km)];
        float2 Ka = kfa[j * 256 + t];
        float2 Kb = kfb[j * 256 + t];
        float2 Kp = make_float2(0.5f * (Ka.x + Kb.x), 0.5f * (Ka.y + Kb.y));
        float2 Km = make_float2(0.5f * (Ka.x - Kb.x), 0.5f * (Ka.y - Kb.y));
        float2 Zmc = make_float2(Zm.x, -Zm.y);
        v[j] = cadd(cmul(v[j], Kp), cmul(Zmc, Km));
    }
    __syncthreads();                            // before overwriting x below

    // ---- inverse 4096 ----
    inv16(v, make_float2(1.f, 0.f));
#pragma unroll
    for (int j = 0; j < 16; j++) x[SIDX(16 * t + j)] = v[j];
    __syncthreads();

#pragma unroll
    for (int j = 0; j < 16; j++) v[j] = x[SIDX(base2 + 16 * j)];
    inv16(v, wp2);
#pragma unroll
    for (int j = 0; j < 16; j++) x[SIDX(base2 + 16 * j)] = v[j];
    __syncthreads();

#pragma unroll
    for (int j = 0; j < 16; j++) v[j] = x[SIDX(t + 256 * j)];
    inv16(v, w1);
    // v[j] = y_a(l) + i*y_b(l) at natural time l = t + 256*j (times NFFT)

    const float Da  = D[2 * hp];
    const float Db  = D[2 * hp + 1];
    const float inv = 1.0f / (float)NFFT;
    float2* yf2 = (float2*)(y + (size_t)b * LSEQ * HCH) + hp;
#pragma unroll
    for (int j = 0; j < 8; j++) {
        float2 out;
        out.x = fmaf(v[j].x, inv, us[j].x * Da);
        out.y = fmaf(v[j].y, inv, us[j].y * Db);
        yf2[(size_t)(t + 256 * j) * (HCH / 2)] = out;
    }
}

// ---------------------------------------------------------------------------
extern "C" void kernel_launch(void* const* d_in, const int* in_sizes, int n_in,
                              void* d_out, int out_size) {
    const float* u   = (const float*)d_in[0];
    const float* Lr  = (const float*)d_in[1];
    const float* Li  = (const float*)d_in[2];
    const float* Pr  = (const float*)d_in[3];
    const float* Pi  = (const float*)d_in[4];
    const float* Br  = (const float*)d_in[5];
    const float* Bi  = (const float*)d_in[6];
    const float* Cr  = (const float*)d_in[7];
    const float* Ci  = (const float*)d_in[8];
    const float* ldt = (const float*)d_in[9];
    const float* D   = (const float*)d_in[10];
    float* y = (float*)d_out;

    const size_t smem = (size_t)SPAD * sizeof(float2);   // 34816 B

    kernel_spec<<<HCH, 256, smem>>>(Lr, Li, Pr, Pi, Br, Bi, Cr, Ci, ldt);
    kernel_conv<<<dim3(HCH / 2, BS), 256, smem>>>(u, D, y);
}

// round 5
// speedup vs baseline: 4.7441x; 1.1922x over previous
#include <cuda_runtime.h>
#include <math.h>

#define HCH  512
#define NST  64
#define BS   8
#define LSEQ 2048
#define NFFT 4096
#define SIDX(i) ((i) + ((i) >> 4))
#define SPAD (NFFT + (NFFT >> 4))   // 4352 float2 = 34816 B

// per-channel spectrum, layout [h][j*256 + t] holding bit-rev position p=16t+j
__device__ float2 d_Kf[(size_t)HCH * NFFT];

// W16^m = exp(-2*pi*i*m/16), m=0..7
__constant__ float2 C16[8] = {
    { 1.0f,           0.0f},
    { 0.92387953251f, -0.38268343236f},
    { 0.70710678119f, -0.70710678119f},
    { 0.38268343236f, -0.92387953251f},
    { 0.0f,          -1.0f},
    {-0.38268343236f, -0.92387953251f},
    {-0.70710678119f, -0.70710678119f},
    {-0.92387953251f, -0.38268343236f},
};

// brev4 lookup (compile-time foldable in unrolled loops)
__constant__ int BR4[16] = {0, 8, 4, 12, 2, 10, 6, 14, 1, 9, 5, 13, 3, 11, 7, 15};

__device__ __forceinline__ float2 cmul(float2 a, float2 b) {
    return make_float2(fmaf(a.x, b.x, -a.y * b.y), fmaf(a.x, b.y, a.y * b.x));
}
__device__ __forceinline__ float2 cmulj(float2 a, float2 b) {   // a * conj(b)
    return make_float2(fmaf(a.x, b.x, a.y * b.y), fmaf(a.y, b.x, -a.x * b.y));
}
__device__ __forceinline__ float2 cadd(float2 a, float2 b) { return make_float2(a.x + b.x, a.y + b.y); }
__device__ __forceinline__ float2 csub(float2 a, float2 b) { return make_float2(a.x - b.x, a.y - b.y); }

// W4096^j = exp(-2*pi*i*j/4096), exact-argument via sincospif
__device__ __forceinline__ float2 tw4096(int j) {
    float s, c;
    sincospif((float)j * (1.0f / 2048.0f), &s, &c);
    return make_float2(c, -s);
}
// conj(W4096^j)
__device__ __forceinline__ float2 tw4096c(int j) {
    float s, c;
    sincospif((float)j * (1.0f / 2048.0f), &s, &c);
    return make_float2(c, s);
}

// ---------------------------------------------------------------------------
// 16-point register FFT blocks (layout: 3 passes = full radix-2 DIF,
// position p ends holding frequency brev12(p)).
// ---------------------------------------------------------------------------
__device__ __forceinline__ void fwd16(float2* v, float2 w1) {
    float2 w2 = cmul(w1, w1), w4 = cmul(w2, w2), w8 = cmul(w4, w4);
#pragma unroll
    for (int j = 0; j < 8; j++) {
        float2 tw = cmul(w1, C16[j]);
        float2 a = v[j], bb = v[j + 8];
        v[j] = cadd(a, bb);
        v[j + 8] = cmul(csub(a, bb), tw);
    }
#pragma unroll
    for (int g = 0; g < 16; g += 8)
#pragma unroll
        for (int j = 0; j < 4; j++) {
            float2 tw = cmul(w2, C16[2 * j]);
            float2 a = v[g + j], bb = v[g + j + 4];
            v[g + j] = cadd(a, bb);
            v[g + j + 4] = cmul(csub(a, bb), tw);
        }
#pragma unroll
    for (int g = 0; g < 16; g += 4)
#pragma unroll
        for (int j = 0; j < 2; j++) {
            float2 tw = cmul(w4, C16[4 * j]);
            float2 a = v[g + j], bb = v[g + j + 2];
            v[g + j] = cadd(a, bb);
            v[g + j + 2] = cmul(csub(a, bb), tw);
        }
#pragma unroll
    for (int g = 0; g < 16; g += 2) {
        float2 a = v[g], bb = v[g + 1];
        v[g] = cadd(a, bb);
        v[g + 1] = cmul(csub(a, bb), w8);
    }
}

__device__ __forceinline__ void inv16(float2* v, float2 w1) {
    float2 c1 = make_float2(w1.x, -w1.y);
    float2 c2 = cmul(c1, c1), c4 = cmul(c2, c2), c8 = cmul(c4, c4);
#pragma unroll
    for (int g = 0; g < 16; g += 2) {
        float2 tb = cmul(v[g + 1], c8);
        float2 a = v[g];
        v[g] = cadd(a, tb);
        v[g + 1] = csub(a, tb);
    }
#pragma unroll
    for (int g = 0; g < 16; g += 4)
#pragma unroll
        for (int j = 0; j < 2; j++) {
            float2 tw = cmulj(c4, C16[4 * j]);
            float2 tb = cmul(v[g + j + 2], tw);
            float2 a = v[g + j];
            v[g + j] = cadd(a, tb);
            v[g + j + 2] = csub(a, tb);
        }
#pragma unroll
    for (int g = 0; g < 16; g += 8)
#pragma unroll
        for (int j = 0; j < 4; j++) {
            float2 tw = cmulj(c2, C16[2 * j]);
            float2 tb = cmul(v[g + j + 4], tw);
            float2 a = v[g + j];
            v[g + j] = cadd(a, tb);
            v[g + j + 4] = csub(a, tb);
        }
#pragma unroll
    for (int j = 0; j < 8; j++) {
        float2 tw = cmulj(c1, C16[j]);
        float2 tb = cmul(v[j + 8], tw);
        float2 a = v[j];
        v[j] = cadd(a, tb);
        v[j + 8] = csub(a, tb);
    }
}

// ---------------------------------------------------------------------------
// Kernel B: per-channel spectral kernel build.
// Cauchy loop exploits conjugate symmetry: one resolvent rcp serves
// frequencies l and 2048-l (lambda[63-n] = conj(lambda[n]) from eigh sort).
// ---------------------------------------------------------------------------
__global__ void __launch_bounds__(256) kernel_spec(
        const float* __restrict__ Lr, const float* __restrict__ Li,
        const float* __restrict__ Pr, const float* __restrict__ Pi,
        const float* __restrict__ Br, const float* __restrict__ Bi,
        const float* __restrict__ Cr, const float* __restrict__ Ci,
        const float* __restrict__ logdt) {
    const int h   = blockIdx.x;
    const int tid = threadIdx.x;

    __shared__ float2 lam[NST], w00[NST], w01[NST], w10[NST];
    __shared__ float  w11[NST];
    extern __shared__ float2 x[];   // SPAD float2

    if (tid < NST) {
        int n = tid;
        lam[n] = make_float2(Lr[n], Li[n]);
        float2 P  = make_float2(Pr[n], Pi[n]);
        float2 Bv = make_float2(Br[n], Bi[n]);
        float2 Cc = make_float2(Cr[h * NST + n], -Ci[h * NST + n]);
        w00[n] = cmul(Cc, Bv);
        w01[n] = cmul(Cc, P);
        float2 Qc = make_float2(P.x, -P.y);
        w10[n] = cmul(Qc, Bv);
        w11[n] = P.x * P.x + P.y * P.y;
    }
    __syncthreads();

    const float dt = expf(logdt[h]);
    const float g0 = 2.0f / dt;

    // ---- at_roots into x[0..2047] (natural order), pairing l with 2048-l ----
    for (int l = tid; l < 1024; l += blockDim.x) {
        // omega = exp(-2*pi*i*l/2048)
        float ss, cc;
        sincospif((float)l * (1.0f / 1024.0f), &ss, &cc);
        float2 om = make_float2(cc, -ss);
        float2 den = make_float2(1.f + om.x, om.y);
        float2 num = make_float2(1.f - om.x, -om.y);
        float idl  = __fdividef(1.f, den.x * den.x + den.y * den.y);
        float2 c2  = make_float2(2.f * den.x * idl, -2.f * den.y * idl);
        float2 gf  = cmul(num, make_float2(den.x, -den.y));
        float2 g   = make_float2(g0 * gf.x * idl, g0 * gf.y * idl);

        float2 a00 = {0.f, 0.f}, a01 = {0.f, 0.f}, a10 = {0.f, 0.f}, a11 = {0.f, 0.f};
        float2 b00 = {0.f, 0.f}, b01 = {0.f, 0.f}, b10 = {0.f, 0.f}, b11 = {0.f, 0.f};
#pragma unroll 4
        for (int n = 0; n < NST; n++) {
            float dx  = g.x - lam[n].x;
            float dy  = g.y - lam[n].y;
            float inv = __fdividef(1.f, dx * dx + dy * dy);
            float2 r  = make_float2(dx * inv, -dy * inv);     // 1/(g - lam_n)
            a00 = cadd(a00, cmul(w00[n], r));
            a01 = cadd(a01, cmul(w01[n], r));
            a10 = cadd(a10, cmul(w10[n], r));
            a11.x = fmaf(w11[n], r.x, a11.x);
            a11.y = fmaf(w11[n], r.y, a11.y);
            // mirror frequency: r' = conj(r), weights at partner index 63-n
            int m = NST - 1 - n;
            float2 rc = make_float2(r.x, -r.y);
            b00 = cadd(b00, cmul(w00[m], rc));
            b01 = cadd(b01, cmul(w01[m], rc));
            b10 = cadd(b10, cmul(w10[m], rc));
            b11.x = fmaf(w11[m], rc.x, b11.x);
            b11.y = fmaf(w11[m], rc.y, b11.y);
        }
        {   // A[l]
            float2 onep = make_float2(1.f + a11.x, a11.y);
            float  ip   = __fdividef(1.f, onep.x * onep.x + onep.y * onep.y);
            float2 invd = make_float2(onep.x * ip, -onep.y * ip);
            float2 t2   = cmul(cmul(a01, a10), invd);
            x[SIDX(l)]  = cmul(c2, csub(a00, t2));
        }
        if (l != 0) {   // A[2048-l], c2' = conj(c2)
            float2 c2c  = make_float2(c2.x, -c2.y);
            float2 onep = make_float2(1.f + b11.x, b11.y);
            float  ip   = __fdividef(1.f, onep.x * onep.x + onep.y * onep.y);
            float2 invd = make_float2(onep.x * ip, -onep.y * ip);
            float2 t2   = cmul(cmul(b01, b10), invd);
            x[SIDX(2048 - l)] = cmul(c2c, csub(b00, t2));
        }
    }
    if (tid == 0) {
        // l = 1024: omega = -1, analytic limit: at -> dt * sum(w00) / 2
        float2 s = make_float2(0.f, 0.f);
        for (int n = 0; n < NST; n++) s = cadd(s, w00[n]);
        x[SIDX(1024)] = make_float2(0.5f * dt * s.x, 0.5f * dt * s.y);
    }
    __syncthreads();

    // ---- inverse FFT 2048 (radix-2 DIF, conj tw): natural -> bit-reversed ----
    {
        int step = 2;
        for (int mh = 1024; mh >= 1; mh >>= 1, step <<= 1) {
            for (int t = tid; t < 1024; t += blockDim.x) {
                int k  = t & (mh - 1);
                int i0 = 2 * t - k, i1 = i0 + mh;
                float2 a = x[SIDX(i0)], b = x[SIDX(i1)];
                x[SIDX(i0)] = cadd(a, b);
                x[SIDX(i1)] = cmul(csub(a, b), tw4096c(k * step));
            }
            __syncthreads();
        }
    }
    // bit-reverse (11-bit) to natural order
    for (int i = tid; i < 2048; i += blockDim.x) {
        int r = __brev(i) >> 21;
        if (r > i) { float2 t = x[SIDX(i)]; x[SIDX(i)] = x[SIDX(r)]; x[SIDX(r)] = t; }
    }
    __syncthreads();
    const float sc = 1.0f / 2048.0f;
    for (int i = tid; i < 2048; i += blockDim.x) {
        float2 t = x[SIDX(i)];
        x[SIDX(i)] = make_float2(t.x * sc, 0.f);
    }
    for (int i = 2048 + tid; i < NFFT; i += blockDim.x) x[SIDX(i)] = make_float2(0.f, 0.f);
    __syncthreads();

    // ---- forward FFT 4096: 3 register-radix-16 passes ----
    float2 v[16];
#pragma unroll
    for (int j = 0; j < 16; j++) v[j] = x[SIDX(tid + 256 * j)];
    fwd16(v, tw4096(tid));
#pragma unroll
    for (int j = 0; j < 16; j++) x[SIDX(tid + 256 * j)] = v[j];
    __syncthreads();

    const int base2 = ((tid >> 4) << 8) + (tid & 15);
#pragma unroll
    for (int j = 0; j < 16; j++) v[j] = x[SIDX(base2 + 16 * j)];
    fwd16(v, tw4096((tid & 15) << 4));
#pragma unroll
    for (int j = 0; j < 16; j++) x[SIDX(base2 + 16 * j)] = v[j];
    __syncthreads();

#pragma unroll
    for (int j = 0; j < 16; j++) v[j] = x[SIDX(16 * tid + j)];
    fwd16(v, make_float2(1.f, 0.f));

    float2* kf = d_Kf + (size_t)h * NFFT;
#pragma unroll
    for (int j = 0; j < 16; j++) kf[j * 256 + tid] = v[j];
}

// ---------------------------------------------------------------------------
// Kernel C: packed two-channel FFT convolution + skip.
// CTA = (h-pair, b). z = u[2h] + i*u[2h+1]; one fwd + one inv FFT per pair.
// S(k) = Z(k)*(Ka+Kb)/2 + conj(Z(N-k))*(Ka-Kb)/2
// __launch_bounds__(256, 2): cap 128 regs so 2 CTAs/SM (occupancy fix).
// ---------------------------------------------------------------------------
__global__ void __launch_bounds__(256, 2) kernel_conv(
        const float* __restrict__ u, const float* __restrict__ D,
        float* __restrict__ y) {
    const int hp = blockIdx.x;                 // channel pair: (2hp, 2hp+1)
    const int b  = blockIdx.y;
    const int t  = threadIdx.x;
    extern __shared__ float2 x[];   // SPAD float2

    // u[b][l][2hp..2hp+1] is a contiguous, 8B-aligned float2
    const float2* uf2 = (const float2*)(u + (size_t)b * LSEQ * HCH) + hp;
    float2 v[16];
#pragma unroll
    for (int j = 0; j < 8; j++)
        v[j] = uf2[(size_t)(t + 256 * j) * (HCH / 2)];
#pragma unroll
    for (int j = 8; j < 16; j++) v[j] = make_float2(0.f, 0.f);

    // ---- forward 4096 ----
    const float2 w1 = tw4096(t);
    fwd16(v, w1);
#pragma unroll
    for (int j = 0; j < 16; j++) x[SIDX(t + 256 * j)] = v[j];
    __syncthreads();

    const int base2 = ((t >> 4) << 8) + (t & 15);
    const float2 wp2 = tw4096((t & 15) << 4);
#pragma unroll
    for (int j = 0; j < 16; j++) v[j] = x[SIDX(base2 + 16 * j)];
    fwd16(v, wp2);
#pragma unroll
    for (int j = 0; j < 16; j++) x[SIDX(base2 + 16 * j)] = v[j];
    __syncthreads();

#pragma unroll
    for (int j = 0; j < 16; j++) v[j] = x[SIDX(16 * t + j)];
    fwd16(v, make_float2(1.f, 0.f));
    // v[j] = Z at position p=16t+j, i.e. frequency k = brev12(p)

    // ---- natural-frequency exchange for Hermitian split ----
    const int rb_t = __brev(t) >> 24;          // brev8(t)
    __syncthreads();                            // others may still be reading pass-3 inputs
#pragma unroll
    for (int j = 0; j < 16; j++)
        x[SIDX((BR4[j] << 8) | rb_t)] = v[j];
    __syncthreads();

    const float2* kfa = d_Kf + (size_t)(2 * hp) * NFFT;
    const float2* kfb = d_Kf + (size_t)(2 * hp + 1) * NFFT;
#pragma unroll
    for (int j = 0; j < 16; j++) {
        int k  = (BR4[j] << 8) | rb_t;
        int km = (NFFT - k) & (NFFT - 1);
        float2 Zm = x[SIDX(km)];
        float2 Ka = kfa[j * 256 + t];
        float2 Kb = kfb[j * 256 + t];
        float2 Kp = make_float2(0.5f * (Ka.x + Kb.x), 0.5f * (Ka.y + Kb.y));
        float2 Km = make_float2(0.5f * (Ka.x - Kb.x), 0.5f * (Ka.y - Kb.y));
        float2 Zmc = make_float2(Zm.x, -Zm.y);
        v[j] = cadd(cmul(v[j], Kp), cmul(Zmc, Km));
    }
    __syncthreads();                            // before overwriting x below

    // ---- inverse 4096 ----
    inv16(v, make_float2(1.f, 0.f));
#pragma unroll
    for (int j = 0; j < 16; j++) x[SIDX(16 * t + j)] = v[j];
    __syncthreads();

#pragma unroll
    for (int j = 0; j < 16; j++) v[j] = x[SIDX(base2 + 16 * j)];
    inv16(v, wp2);
#pragma unroll
    for (int j = 0; j < 16; j++) x[SIDX(base2 + 16 * j)] = v[j];
    __syncthreads();

#pragma unroll
    for (int j = 0; j < 16; j++) v[j] = x[SIDX(t + 256 * j)];
    inv16(v, w1);
    // v[j] = y_a(l) + i*y_b(l) at natural time l = t + 256*j (times NFFT)

    const float Da  = D[2 * hp];
    const float Db  = D[2 * hp + 1];
    const float inv = 1.0f / (float)NFFT;
    float2* yf2 = (float2*)(y + (size_t)b * LSEQ * HCH) + hp;
#pragma unroll
    for (int j = 0; j < 8; j++) {
        float2 uu = uf2[(size_t)(t + 256 * j) * (HCH / 2)];   // reload (saves 16 regs)
        float2 out;
        out.x = fmaf(v[j].x, inv, uu.x * Da);
        out.y = fmaf(v[j].y, inv, uu.y * Db);
        yf2[(size_t)(t + 256 * j) * (HCH / 2)] = out;
    }
}

// ---------------------------------------------------------------------------
extern "C" void kernel_launch(void* const* d_in, const int* in_sizes, int n_in,
                              void* d_out, int out_size) {
    const float* u   = (const float*)d_in[0];
    const float* Lr  = (const float*)d_in[1];
    const float* Li  = (const float*)d_in[2];
    const float* Pr  = (const float*)d_in[3];
    const float* Pi  = (const float*)d_in[4];
    const float* Br  = (const float*)d_in[5];
    const float* Bi  = (const float*)d_in[6];
    const float* Cr  = (const float*)d_in[7];
    const float* Ci  = (const float*)d_in[8];
    const float* ldt = (const float*)d_in[9];
    const float* D   = (const float*)d_in[10];
    float* y = (float*)d_out;

    const size_t smem = (size_t)SPAD * sizeof(float2);   // 34816 B

    kernel_spec<<<HCH, 256, smem>>>(Lr, Li, Pr, Pi, Br, Bi, Cr, Ci, ldt);
    kernel_conv<<<dim3(HCH / 2, BS), 256, smem>>>(u, D, y);
}